// round 2
// baseline (speedup 1.0000x reference)
#include <cuda_runtime.h>
#include <cstdint>

#define KNN 5
#define TPB 256
#define F_INF __int_as_float(0x7f800000)

// Decode a scalar that may be stored as int32 or float32 bits.
__device__ __forceinline__ float decode_scalar_f(const void* p) {
    int iv = *(const int*)p;
    if (iv >= -1000000 && iv <= 1000000) return (float)iv;  // plausible int
    return __int_as_float(iv);                              // else float bits
}

__global__ void __launch_bounds__(TPB, 3) upsample_flow_knn_kernel(
    const float* __restrict__ xyz,     // [B,3,N]
    const float* __restrict__ sxyz,    // [B,3,M]
    const float* __restrict__ sflow,   // [B,3,M]
    const void* __restrict__ rf_ptr,   // scalar resol_factor
    float* __restrict__ out,           // [B,3,N]
    int N, int M)
{
    extern __shared__ float4 sp[];     // (x,y,z,|p|^2) scaled, M entries

    const int b = blockIdx.y;
    const int n = blockIdx.x * blockDim.x + threadIdx.x;

    const float sigma = rf_ptr ? decode_scalar_f(rf_ptr) : 1.0f;
    const float inv_sigma = 1.0f / sigma;

    // Cooperative load of scaled sparse points + squared norms into smem.
    {
        const float* P = sxyz + (size_t)b * 3 * M;
        for (int j = threadIdx.x; j < M; j += blockDim.x) {
            float x = P[j]         * inv_sigma;
            float y = P[M + j]     * inv_sigma;
            float z = P[2 * M + j] * inv_sigma;
            sp[j] = make_float4(x, y, z, fmaf(x, x, fmaf(y, y, z * z)));
        }
    }
    __syncthreads();

    if (n >= N) return;

    // Query point (scaled).
    const size_t qbase = (size_t)b * 3 * N;
    const float qx = xyz[qbase + n]         * inv_sigma;
    const float qy = xyz[qbase + N + n]     * inv_sigma;
    const float qz = xyz[qbase + 2 * N + n] * inv_sigma;
    const float m2x = -2.0f * qx;
    const float m2y = -2.0f * qy;
    const float m2z = -2.0f * qz;

    // Top-K smallest surrogate s = |p|^2 - 2 q.p  (equals sqdist - |q|^2).
    float best[KNN];
    int   bidx[KNN];
#pragma unroll
    for (int k = 0; k < KNN; k++) { best[k] = F_INF; bidx[k] = 0; }
    float worst = F_INF;
    int   wslot = 0;

#pragma unroll 4
    for (int j = 0; j < M; j++) {
        float4 p = sp[j];
        float s = fmaf(m2x, p.x, p.w);
        s = fmaf(m2y, p.y, s);
        s = fmaf(m2z, p.z, s);
        if (s < worst) {
            // predicated register writes (no dynamic indexing -> no spill)
#pragma unroll
            for (int k = 0; k < KNN; k++)
                if (k == wslot) { best[k] = s; bidx[k] = j; }
            // rescan for the new worst
            worst = best[0]; wslot = 0;
#pragma unroll
            for (int k = 1; k < KNN; k++)
                if (best[k] > worst) { worst = best[k]; wslot = k; }
        }
    }

    // True distances for the K winners.
    const float q2 = fmaf(qx, qx, fmaf(qy, qy, qz * qz));
    float d[KNN];
    float dmin = F_INF;
#pragma unroll
    for (int k = 0; k < KNN; k++) {
        d[k] = sqrtf(fmaxf(q2 + best[k], 1e-12f));
        dmin = fminf(dmin, d[k]);
    }

    // Softmax over -d (stable: subtract max of -d, i.e. -dmin) + flow gather.
    const float* FL = sflow + (size_t)b * 3 * M;
    float wsum = 0.0f, fx = 0.0f, fy = 0.0f, fz = 0.0f;
#pragma unroll
    for (int k = 0; k < KNN; k++) {
        float w = __expf(dmin - d[k]);
        wsum += w;
        int j = bidx[k];
        fx = fmaf(w, FL[j],         fx);
        fy = fmaf(w, FL[M + j],     fy);
        fz = fmaf(w, FL[2 * M + j], fz);
    }
    const float inv = 1.0f / wsum;

    out[qbase + n]         = fx * inv;
    out[qbase + N + n]     = fy * inv;
    out[qbase + 2 * N + n] = fz * inv;
}

extern "C" void kernel_launch(void* const* d_in, const int* in_sizes, int n_in,
                              void* d_out, int out_size) {
    const float* xyz   = (const float*)d_in[0];
    const float* sxyz  = (const float*)d_in[1];
    const float* sflow = (const float*)d_in[2];
    const void*  rf    = (n_in > 3) ? d_in[3] : nullptr;
    float* out = (float*)d_out;

    const int B = 4;
    const int N = in_sizes[0] / (3 * B);   // 16384
    const int M = in_sizes[1] / (3 * B);   // 4096

    const size_t smem = (size_t)M * sizeof(float4);  // 64 KB
    static bool attr_set = false;
    if (!attr_set) {
        cudaFuncSetAttribute(upsample_flow_knn_kernel,
                             cudaFuncAttributeMaxDynamicSharedMemorySize,
                             (int)smem);
        attr_set = true;
    }

    dim3 block(TPB, 1, 1);
    dim3 grid((N + TPB - 1) / TPB, B, 1);
    upsample_flow_knn_kernel<<<grid, block, smem>>>(xyz, sxyz, sflow, rf, out, N, M);
}